// round 15
// baseline (speedup 1.0000x reference)
#include <cuda_runtime.h>
#include <cstddef>
#include <cstdint>

// FISM scoring: B=16384, K=50, NNEG=20, D=128. Warp-per-row fused kernel.
// R15 = R13/R14 v8 kernel with the redistribution SHFL BUG FIXED:
// a shfl transmits the SOURCE lane's selected value, so selecting c[0..3] vs
// c[4..7] with the source's (lane&1) was wrong — must shuffle both halves and
// select with the DESTINATION's bit. (R14 failed rel_err=4.6e-2 from this.)
// Gather: ld.global.nc.L2::evict_last.v8.b32 — one LDG.256 loads TWO rows
// (lanes 0-15 row 2k, lanes 16-31 row 2k+1, 32B/lane) -> 2x bytes-in-flight
// per register; launch_bounds(256,4) for the 64-reg budget.
// Phase 2 (21 dots, shfl broadcast + butterfly) is EXACTLY R6.
// Fallbacks: 16B-aligned -> R6 float4 kernel; else scalar.

#define FB    16384
#define FK    50
#define FNNEG 20
#define FD    128
#define WPB   8                      // warps (rows) per 256-thread block

// float4 gather with L2 evict_last cache hint (proven R6 path)
__device__ __forceinline__ float4 ldg_el4(const float4* p) {
    float4 v;
    asm("{\n\t"
        ".reg .b64 pol;\n\t"
        "createpolicy.fractional.L2::evict_last.b64 pol, 1.0;\n\t"
        "ld.global.nc.L2::cache_hint.v4.f32 {%0,%1,%2,%3}, [%4], pol;\n\t"
        "}"
        : "=f"(v.x), "=f"(v.y), "=f"(v.z), "=f"(v.w) : "l"(p));
    return v;
}

// 256-bit load with direct evict_last modifier (v8.b32 form)
__device__ __forceinline__ void ldg_el8(const float* p, float* c) {
    uint32_t r0, r1, r2, r3, r4, r5, r6, r7;
    asm("ld.global.nc.L2::evict_last.v8.b32 {%0,%1,%2,%3,%4,%5,%6,%7}, [%8];"
        : "=r"(r0), "=r"(r1), "=r"(r2), "=r"(r3),
          "=r"(r4), "=r"(r5), "=r"(r6), "=r"(r7) : "l"(p));
    c[0] += __uint_as_float(r0); c[1] += __uint_as_float(r1);
    c[2] += __uint_as_float(r2); c[3] += __uint_as_float(r3);
    c[4] += __uint_as_float(r4); c[5] += __uint_as_float(r5);
    c[6] += __uint_as_float(r6); c[7] += __uint_as_float(r7);
}

// ---------------- primary kernel: 32B-aligned tables ---------------------
__global__ __launch_bounds__(256, 4) void fism_v8(
    const int*   __restrict__ I,
    const int*   __restrict__ U,
    const int*   __restrict__ I_neg,
    const int*   __restrict__ I_U,
    const int*   __restrict__ N_U,
    const int*   __restrict__ I_in,
    const float* __restrict__ P,
    const float* __restrict__ Q,
    const float* __restrict__ b_u,
    const float* __restrict__ b_i,
    float*       __restrict__ out)
{
    const int wid  = threadIdx.x >> 5;
    const int lane = threadIdx.x & 31;
    const int b    = blockIdx.x * WPB + wid;     // FB = 2048*8 exact

    __shared__ int s_idx[WPB][FK];
    {
        const int* src = I_U + (size_t)b * FK;
        s_idx[wid][lane] = src[lane];
        if (lane < FK - 32) s_idx[wid][32 + lane] = src[32 + lane];
    }
    __syncwarp();

    // hoisted scalars (latency hides under the gather)
    const int   i_pos = __ldg(&I[b]);
    const float ind   = (float)__ldg(&I_in[b]);
    const float n_u   = (float)__ldg(&N_U[b]);
    const float bu    = __ldg(&b_u[__ldg(&U[b])]);
    const int   negi  = (lane < FNNEG) ? __ldg(&I_neg[(size_t)b * FNNEG + lane]) : 0;
    const float bi_n  = (lane < FNNEG) ? __ldg(&b_i[negi]) : 0.0f;
    const float bi_p  = __ldg(&b_i[i_pos]);

    // ---- gather: 25 x LDG.256, each covering two rows --------------------
    // lanes 0-15: rows 2k, dims [8*lsub .. 8*lsub+7]; lanes 16-31: rows 2k+1
    const int rsel = lane >> 4;          // 0 or 1
    const int lsub = lane & 15;
    float c[8] = {0.f,0.f,0.f,0.f,0.f,0.f,0.f,0.f};
    #pragma unroll
    for (int k = 0; k < FK / 2; k++) {
        const int idx = s_idx[wid][2 * k + rsel];
        ldg_el8(P + (size_t)idx * FD + lsub * 8, c);
    }
    // pair-sum: after this, lane l holds FULL neighbor sum for dims
    // [8*lsub .. 8*lsub+7] (duplicated in lane l^16)
    #pragma unroll
    for (int j = 0; j < 8; j++)
        c[j] += __shfl_xor_sync(0xffffffffu, c[j], 16);

    // redistribute to float4-per-lane layout: lane m wants dims[4m..4m+3],
    // held by lane (m>>1) as c[4*(m&1) .. 4*(m&1)+3].
    // FIX: shuffle BOTH halves, select with the DESTINATION's bit (m&1) —
    // shfl transmits the source lane's value, so source-side selection is wrong.
    const int srcl = lane >> 1;
    const int hi   = lane & 1;
    const float lo0 = __shfl_sync(0xffffffffu, c[0], srcl);
    const float lo1 = __shfl_sync(0xffffffffu, c[1], srcl);
    const float lo2 = __shfl_sync(0xffffffffu, c[2], srcl);
    const float lo3 = __shfl_sync(0xffffffffu, c[3], srcl);
    const float hi0 = __shfl_sync(0xffffffffu, c[4], srcl);
    const float hi1 = __shfl_sync(0xffffffffu, c[5], srcl);
    const float hi2 = __shfl_sync(0xffffffffu, c[6], srcl);
    const float hi3 = __shfl_sync(0xffffffffu, c[7], srcl);
    float a0 = hi ? hi0 : lo0;
    float a1 = hi ? hi1 : lo1;
    float a2 = hi ? hi2 : lo2;
    float a3 = hi ? hi3 : lo3;

    {   // exclude self if present (float4 path; 32B-aligned implies 16B)
        const float4 v = ldg_el4(reinterpret_cast<const float4*>(P + (size_t)i_pos * FD) + lane);
        a0 -= v.x * ind; a1 -= v.y * ind; a2 -= v.z * ind; a3 -= v.w * ind;
    }

    const float inv = 1.0f / fmaxf(n_u - ind, 1.0f);   // ALPHA = 1
    const float p0 = a0 * inv, p1 = a1 * inv, p2 = a2 * inv, p3 = a3 * inv;

    // ---- 21 dot products (EXACT R6 structure) ----------------------------
    float my_neg = 0.0f;
    float r_pos  = 0.0f;
    #pragma unroll
    for (int t = 0; t < 1 + FNNEG; t++) {
        const int item = (t == 0) ? i_pos : __shfl_sync(0xffffffffu, negi, t - 1);
        const float4 v = ldg_el4(reinterpret_cast<const float4*>(Q + (size_t)item * FD) + lane);
        float d = p0 * v.x + p1 * v.y + p2 * v.z + p3 * v.w;
        #pragma unroll
        for (int off = 16; off > 0; off >>= 1)
            d += __shfl_xor_sync(0xffffffffu, d, off);
        if (t == 0)               r_pos  = d;
        else if (lane == t - 1)   my_neg = d;
    }

    if (lane < FNNEG)
        out[FB + (size_t)b * FNNEG + lane] = bu + bi_n + my_neg;
    if (lane == 0)
        out[b] = bu + bi_p + r_pos;
}

// ---------------- fallback kernel (R6 exact): VEC=16B-aligned ------------
template<bool VEC>
__global__ __launch_bounds__(256, 5) void fism_fused(
    const int*   __restrict__ I,
    const int*   __restrict__ U,
    const int*   __restrict__ I_neg,
    const int*   __restrict__ I_U,
    const int*   __restrict__ N_U,
    const int*   __restrict__ I_in,
    const float* __restrict__ P,
    const float* __restrict__ Q,
    const float* __restrict__ b_u,
    const float* __restrict__ b_i,
    float*       __restrict__ out)
{
    const int wid  = threadIdx.x >> 5;
    const int lane = threadIdx.x & 31;
    const int b    = blockIdx.x * WPB + wid;

    __shared__ int s_idx[WPB][FK];
    {
        const int* src = I_U + (size_t)b * FK;
        s_idx[wid][lane] = src[lane];
        if (lane < FK - 32) s_idx[wid][32 + lane] = src[32 + lane];
    }
    __syncwarp();

    const int   i_pos = __ldg(&I[b]);
    const float ind   = (float)__ldg(&I_in[b]);
    const float n_u   = (float)__ldg(&N_U[b]);
    const float bu    = __ldg(&b_u[__ldg(&U[b])]);
    const int   negi  = (lane < FNNEG) ? __ldg(&I_neg[(size_t)b * FNNEG + lane]) : 0;
    const float bi_n  = (lane < FNNEG) ? __ldg(&b_i[negi]) : 0.0f;
    const float bi_p  = __ldg(&b_i[i_pos]);

    float a0 = 0.f, a1 = 0.f, a2 = 0.f, a3 = 0.f;
    #pragma unroll
    for (int k = 0; k < FK; k++) {
        const float* row = P + (size_t)s_idx[wid][k] * FD;
        if (VEC) {
            const float4 v = ldg_el4(reinterpret_cast<const float4*>(row) + lane);
            a0 += v.x; a1 += v.y; a2 += v.z; a3 += v.w;
        } else {
            a0 += __ldg(&row[lane]);
            a1 += __ldg(&row[lane + 32]);
            a2 += __ldg(&row[lane + 64]);
            a3 += __ldg(&row[lane + 96]);
        }
    }
    {
        const float* row = P + (size_t)i_pos * FD;
        if (VEC) {
            const float4 v = ldg_el4(reinterpret_cast<const float4*>(row) + lane);
            a0 -= v.x * ind; a1 -= v.y * ind; a2 -= v.z * ind; a3 -= v.w * ind;
        } else {
            a0 -= __ldg(&row[lane])      * ind;
            a1 -= __ldg(&row[lane + 32]) * ind;
            a2 -= __ldg(&row[lane + 64]) * ind;
            a3 -= __ldg(&row[lane + 96]) * ind;
        }
    }

    const float inv = 1.0f / fmaxf(n_u - ind, 1.0f);
    const float p0 = a0 * inv, p1 = a1 * inv, p2 = a2 * inv, p3 = a3 * inv;

    float my_neg = 0.0f;
    float r_pos  = 0.0f;
    #pragma unroll
    for (int t = 0; t < 1 + FNNEG; t++) {
        const int item = (t == 0) ? i_pos : __shfl_sync(0xffffffffu, negi, t - 1);
        const float* qr = Q + (size_t)item * FD;
        float d;
        if (VEC) {
            const float4 v = ldg_el4(reinterpret_cast<const float4*>(qr) + lane);
            d = p0 * v.x + p1 * v.y + p2 * v.z + p3 * v.w;
        } else {
            d = p0 * __ldg(&qr[lane])
              + p1 * __ldg(&qr[lane + 32])
              + p2 * __ldg(&qr[lane + 64])
              + p3 * __ldg(&qr[lane + 96]);
        }
        #pragma unroll
        for (int off = 16; off > 0; off >>= 1)
            d += __shfl_xor_sync(0xffffffffu, d, off);
        if (t == 0)               r_pos  = d;
        else if (lane == t - 1)   my_neg = d;
    }

    if (lane < FNNEG)
        out[FB + (size_t)b * FNNEG + lane] = bu + bi_n + my_neg;
    if (lane == 0)
        out[b] = bu + bi_p + r_pos;
}

extern "C" void kernel_launch(void* const* d_in, const int* in_sizes, int n_in,
                              void* d_out, int out_size)
{
    const int*   I     = (const int*)  d_in[0];
    const int*   U     = (const int*)  d_in[1];
    const int*   I_neg = (const int*)  d_in[2];
    const int*   I_U   = (const int*)  d_in[3];
    const int*   N_U   = (const int*)  d_in[4];
    const int*   I_in  = (const int*)  d_in[5];
    const float* P     = (const float*)d_in[6];
    const float* Q     = (const float*)d_in[7];
    const float* b_u   = (const float*)d_in[8];
    const float* b_i   = (const float*)d_in[9];
    float* out = (float*)d_out;

    const bool a32 = (((uintptr_t)P & 31u) == 0) && (((uintptr_t)Q & 15u) == 0);
    const bool a16 = (((uintptr_t)P & 15u) == 0) && (((uintptr_t)Q & 15u) == 0);
    dim3 grid(FB / WPB), block(32 * WPB);

    if (a32)
        fism_v8<<<grid, block>>>(I, U, I_neg, I_U, N_U, I_in, P, Q, b_u, b_i, out);
    else if (a16)
        fism_fused<true ><<<grid, block>>>(I, U, I_neg, I_U, N_U, I_in, P, Q, b_u, b_i, out);
    else
        fism_fused<false><<<grid, block>>>(I, U, I_neg, I_U, N_U, I_in, P, Q, b_u, b_i, out);
}